// round 13
// baseline (speedup 1.0000x reference)
#include <cuda_runtime.h>
#include <cuda_fp16.h>
#include <cuda_bf16.h>

// WeightedBiasEncoder: out[B*H, N+1, N+1]
//   out[bh][0][*] = token[h];  out[bh][r][0] = token[h] (r>=1)
//   out[bh][r][c] = emb[spatial[(b*N + r-1)*N + (c-1)]][h]   (r,c >= 1)
//
// H==8, N==512 fast path. Model (R2-R12): lane-contiguous STG.32 only store
// shape; gather = 1 LDS.128/elt via fp16 table (pre-scaled 2^17, inverse
// exact, rel err <= 2^-11); spatial LDGs hoisted above the table prologue
// (R10); __stcs evict-first on the 135MB output stream (R12 win — steady
// state is write-drain bound); registers > occupancy for latency hiding
// (R10 vs R11). R13: 8 rows/block, 64 lanes/row -> 8 front-batched LDGs per
// thread (MLP 4->8), half the prologues, stores still 1 wavefront/warp.

#define TPB 512
#define SCALE_UP   131072.0f            // 2^17
#define SCALE_DOWN 7.62939453125e-06f   // 2^-17 (exact)

__global__ __launch_bounds__(TPB) void wbe_fast8(
    const int*   __restrict__ spatial,   // [B*N*N]
    const float* __restrict__ emb,       // [SP1, 8]
    const float* __restrict__ token,     // [8]
    float*       __restrict__ out,       // [B*8, N+1, N+1]
    int N, int SP1)
{
    __shared__ __align__(16) __half2 tab[4 * 256];   // entry s -> tab[4s..4s+3]
    const int tid = threadIdx.x;
    const int bx  = blockIdx.x;
    const int b   = blockIdx.y;
    const unsigned P  = (unsigned)N + 1u;
    const unsigned P2 = P * P;
    const unsigned planeb = (unsigned)(b * 8) * P2;

    // interior row for this 64-lane group (valid only when bx >= 1)
    const int r  = 8 * (bx - 1) + 1 + (tid >> 6);
    const int ct = tid & 63;

    // ---- issue spatial loads FIRST: latency hides behind table prologue ----
    int s[8];
    const int* __restrict__ srow =
        spatial + ((size_t)b * (size_t)N + (size_t)(r - 1)) * (size_t)N;
    if (bx > 0) {
        #pragma unroll
        for (int k = 0; k < 8; k++)
            s[k] = __ldg(srow + ct + k * 64);
    }

    // ---- table prologue (fp16, scaled) ----
    if (tid < SP1) {
        const float4 a = ((const float4*)emb)[2 * tid];
        const float4 c = ((const float4*)emb)[2 * tid + 1];
        tab[4 * tid + 0] = __floats2half2_rn(a.x * SCALE_UP, a.y * SCALE_UP);
        tab[4 * tid + 1] = __floats2half2_rn(a.z * SCALE_UP, a.w * SCALE_UP);
        tab[4 * tid + 2] = __floats2half2_rn(c.x * SCALE_UP, c.y * SCALE_UP);
        tab[4 * tid + 3] = __floats2half2_rn(c.z * SCALE_UP, c.w * SCALE_UP);
    }
    __syncthreads();

    if (bx == 0) {
        // graph-token row (row 0) for all 8 heads (exact fp32)
        #pragma unroll
        for (int h = 0; h < 8; h++) {
            const float tv = token[h];
            for (unsigned c = tid; c < P; c += TPB)
                __stcs(&out[planeb + (unsigned)h * P2 + c], tv);
        }
        return;
    }

    float* __restrict__ o = out + planeb + (unsigned)r * P + 1;

    #pragma unroll
    for (int k = 0; k < 8; k++) {
        // ONE LDS.128 fetches all 8 heads (fp16)
        const uint4 raw = *reinterpret_cast<const uint4*>(tab + 4 * s[k]);
        const float2 f0 = __half22float2(*reinterpret_cast<const __half2*>(&raw.x));
        const float2 f1 = __half22float2(*reinterpret_cast<const __half2*>(&raw.y));
        const float2 f2 = __half22float2(*reinterpret_cast<const __half2*>(&raw.z));
        const float2 f3 = __half22float2(*reinterpret_cast<const __half2*>(&raw.w));
        float* __restrict__ q = o + ct + k * 64;
        __stcs(q + 0u * P2, f0.x * SCALE_DOWN);
        __stcs(q + 1u * P2, f0.y * SCALE_DOWN);
        __stcs(q + 2u * P2, f1.x * SCALE_DOWN);
        __stcs(q + 3u * P2, f1.y * SCALE_DOWN);
        __stcs(q + 4u * P2, f2.x * SCALE_DOWN);
        __stcs(q + 5u * P2, f2.y * SCALE_DOWN);
        __stcs(q + 6u * P2, f3.x * SCALE_DOWN);
        __stcs(q + 7u * P2, f3.y * SCALE_DOWN);
    }

    // graph-token column (col 0) for this row, all 8 heads (off critical path)
    if (ct < 8)
        __stcs(&out[planeb + (unsigned)ct * P2 + (unsigned)r * P], token[ct]);
}

// Generic fallback (H != 8, table too big, or N != 512) — exact fp32 path.
#define G_ROWS 4
#define G_TPB 256

__global__ __launch_bounds__(G_TPB) void wbe_generic(
    const int*   __restrict__ spatial,
    const float* __restrict__ emb,
    const float* __restrict__ token,
    float*       __restrict__ out,
    int N, int H, int SP1)
{
    __shared__ float emb_s[4096];
    const int tid = threadIdx.x;
    int total = SP1 * H;
    if (total > 4096) total = 4096;
    for (int idx = tid; idx < total; idx += G_TPB) {
        int h = idx / SP1;
        int s = idx - h * SP1;
        emb_s[idx] = emb[s * H + h];
    }
    __syncthreads();

    const unsigned bh = blockIdx.y;
    const int h = (int)(bh % (unsigned)H);
    const int b = (int)(bh / (unsigned)H);
    const float tokv = token[h];
    const unsigned P  = (unsigned)N + 1u;
    const unsigned P2 = P * P;
    const float* __restrict__ eh = emb_s + h * SP1;
    float* __restrict__ plane = out + (size_t)bh * (size_t)P2;

    #pragma unroll
    for (int rr = 0; rr < G_ROWS; rr++) {
        const unsigned r = blockIdx.x * G_ROWS + rr;
        if (r >= P) return;
        float* __restrict__ orow = plane + (size_t)r * P;
        if (r == 0) {
            for (unsigned c = tid; c < P; c += G_TPB) orow[c] = tokv;
        } else {
            if (tid == 0) orow[0] = tokv;
            const int* __restrict__ srow =
                spatial + ((size_t)b * (size_t)N + (size_t)(r - 1)) * (size_t)N;
            for (unsigned c = tid; c < (unsigned)N; c += G_TPB)
                orow[1 + c] = eh[srow[c]];
        }
    }
}

extern "C" void kernel_launch(void* const* d_in, const int* in_sizes, int n_in,
                              void* d_out, int out_size)
{
    const int*   spatial = (const int*)  d_in[0];
    const float* emb     = (const float*)d_in[n_in - 2];
    const float* token   = (const float*)d_in[n_in - 1];

    const int E         = in_sizes[0];          // B*N*N
    const int num_nodes = in_sizes[2];          // B*N
    const int H         = in_sizes[n_in - 1];
    const int SP1       = in_sizes[n_in - 2] / H;
    const int N         = E / num_nodes;
    const int B         = num_nodes / N;
    const int P         = N + 1;

    if (H == 8 && SP1 <= 256 && N == 512) {
        dim3 grid((unsigned)(N / 8 + 1), (unsigned)B);   // 65 x 16 = 1040 blocks
        wbe_fast8<<<grid, TPB>>>(spatial, emb, token, (float*)d_out, N, SP1);
    } else {
        dim3 grid((P + G_ROWS - 1) / G_ROWS, (unsigned)(B * H));
        wbe_generic<<<grid, G_TPB>>>(spatial, emb, token, (float*)d_out, N, H, SP1);
    }
}

// round 14
// speedup vs baseline: 1.2220x; 1.2220x over previous
#include <cuda_runtime.h>
#include <cuda_fp16.h>
#include <cuda_bf16.h>

// WeightedBiasEncoder: out[B*H, N+1, N+1]
//   out[bh][0][*] = token[h];  out[bh][r][0] = token[h] (r>=1)
//   out[bh][r][c] = emb[spatial[(b*N + r-1)*N + (c-1)]][h]   (r,c >= 1)
//
// H==8, N==512 fast path. Model (R2-R13): lane-contiguous STG.32 only store
// shape; gather = 1 LDS.128/elt via fp16 table (pre-scaled 2^17, inverse
// exact, rel err <= 2^-11); spatial LDGs hoisted above the table prologue
// (R10 win); __stcs evict-first on the output stream (R12 win, steady state
// is write-drain bound); grid must stay well over-subscribed — >= ~2k blocks
// (R8/R13 losses); MLP=4/thread is the sweet spot (R13). R14: TPB 256,
// 2 rows/block -> 4112 blocks (2x R12) with the same winning body.

#define TPB 256
#define SCALE_UP   131072.0f            // 2^17
#define SCALE_DOWN 7.62939453125e-06f   // 2^-17 (exact)

__global__ __launch_bounds__(TPB) void wbe_fast8(
    const int*   __restrict__ spatial,   // [B*N*N]
    const float* __restrict__ emb,       // [SP1, 8]
    const float* __restrict__ token,     // [8]
    float*       __restrict__ out,       // [B*8, N+1, N+1]
    int N, int SP1)
{
    __shared__ __align__(16) __half2 tab[4 * 256];   // entry s -> tab[4s..4s+3]
    const int tid = threadIdx.x;
    const int bx  = blockIdx.x;
    const int b   = blockIdx.y;
    const unsigned P  = (unsigned)N + 1u;
    const unsigned P2 = P * P;
    const unsigned planeb = (unsigned)(b * 8) * P2;

    // interior row for this 128-lane group (valid only when bx >= 1)
    const int r  = 2 * (bx - 1) + 1 + (tid >> 7);
    const int ct = tid & 127;

    // ---- issue spatial loads FIRST: latency hides behind table prologue ----
    int s[4];
    const int* __restrict__ srow =
        spatial + ((size_t)b * (size_t)N + (size_t)(r - 1)) * (size_t)N;
    if (bx > 0) {
        #pragma unroll
        for (int k = 0; k < 4; k++)
            s[k] = __ldg(srow + ct + k * 128);
    }

    // ---- table prologue (fp16, scaled) ----
    if (tid < SP1) {
        const float4 a = ((const float4*)emb)[2 * tid];
        const float4 c = ((const float4*)emb)[2 * tid + 1];
        tab[4 * tid + 0] = __floats2half2_rn(a.x * SCALE_UP, a.y * SCALE_UP);
        tab[4 * tid + 1] = __floats2half2_rn(a.z * SCALE_UP, a.w * SCALE_UP);
        tab[4 * tid + 2] = __floats2half2_rn(c.x * SCALE_UP, c.y * SCALE_UP);
        tab[4 * tid + 3] = __floats2half2_rn(c.z * SCALE_UP, c.w * SCALE_UP);
    }
    __syncthreads();

    if (bx == 0) {
        // graph-token row (row 0) for all 8 heads (exact fp32)
        #pragma unroll
        for (int h = 0; h < 8; h++) {
            const float tv = token[h];
            for (unsigned c = tid; c < P; c += TPB)
                __stcs(&out[planeb + (unsigned)h * P2 + c], tv);
        }
        return;
    }

    float* __restrict__ o = out + planeb + (unsigned)r * P + 1;

    #pragma unroll
    for (int k = 0; k < 4; k++) {
        // ONE LDS.128 fetches all 8 heads (fp16)
        const uint4 raw = *reinterpret_cast<const uint4*>(tab + 4 * s[k]);
        const float2 f0 = __half22float2(*reinterpret_cast<const __half2*>(&raw.x));
        const float2 f1 = __half22float2(*reinterpret_cast<const __half2*>(&raw.y));
        const float2 f2 = __half22float2(*reinterpret_cast<const __half2*>(&raw.z));
        const float2 f3 = __half22float2(*reinterpret_cast<const __half2*>(&raw.w));
        float* __restrict__ q = o + ct + k * 128;
        __stcs(q + 0u * P2, f0.x * SCALE_DOWN);
        __stcs(q + 1u * P2, f0.y * SCALE_DOWN);
        __stcs(q + 2u * P2, f1.x * SCALE_DOWN);
        __stcs(q + 3u * P2, f1.y * SCALE_DOWN);
        __stcs(q + 4u * P2, f2.x * SCALE_DOWN);
        __stcs(q + 5u * P2, f2.y * SCALE_DOWN);
        __stcs(q + 6u * P2, f3.x * SCALE_DOWN);
        __stcs(q + 7u * P2, f3.y * SCALE_DOWN);
    }

    // graph-token column (col 0) for this row, all 8 heads (off critical path)
    if (ct < 8)
        __stcs(&out[planeb + (unsigned)ct * P2 + (unsigned)r * P], token[ct]);
}

// Generic fallback (H != 8, table too big, or N != 512) — exact fp32 path.
#define G_ROWS 4
#define G_TPB 256

__global__ __launch_bounds__(G_TPB) void wbe_generic(
    const int*   __restrict__ spatial,
    const float* __restrict__ emb,
    const float* __restrict__ token,
    float*       __restrict__ out,
    int N, int H, int SP1)
{
    __shared__ float emb_s[4096];
    const int tid = threadIdx.x;
    int total = SP1 * H;
    if (total > 4096) total = 4096;
    for (int idx = tid; idx < total; idx += G_TPB) {
        int h = idx / SP1;
        int s = idx - h * SP1;
        emb_s[idx] = emb[s * H + h];
    }
    __syncthreads();

    const unsigned bh = blockIdx.y;
    const int h = (int)(bh % (unsigned)H);
    const int b = (int)(bh / (unsigned)H);
    const float tokv = token[h];
    const unsigned P  = (unsigned)N + 1u;
    const unsigned P2 = P * P;
    const float* __restrict__ eh = emb_s + h * SP1;
    float* __restrict__ plane = out + (size_t)bh * (size_t)P2;

    #pragma unroll
    for (int rr = 0; rr < G_ROWS; rr++) {
        const unsigned r = blockIdx.x * G_ROWS + rr;
        if (r >= P) return;
        float* __restrict__ orow = plane + (size_t)r * P;
        if (r == 0) {
            for (unsigned c = tid; c < P; c += G_TPB) orow[c] = tokv;
        } else {
            if (tid == 0) orow[0] = tokv;
            const int* __restrict__ srow =
                spatial + ((size_t)b * (size_t)N + (size_t)(r - 1)) * (size_t)N;
            for (unsigned c = tid; c < (unsigned)N; c += G_TPB)
                orow[1 + c] = eh[srow[c]];
        }
    }
}

extern "C" void kernel_launch(void* const* d_in, const int* in_sizes, int n_in,
                              void* d_out, int out_size)
{
    const int*   spatial = (const int*)  d_in[0];
    const float* emb     = (const float*)d_in[n_in - 2];
    const float* token   = (const float*)d_in[n_in - 1];

    const int E         = in_sizes[0];          // B*N*N
    const int num_nodes = in_sizes[2];          // B*N
    const int H         = in_sizes[n_in - 1];
    const int SP1       = in_sizes[n_in - 2] / H;
    const int N         = E / num_nodes;
    const int B         = num_nodes / N;
    const int P         = N + 1;

    if (H == 8 && SP1 <= 256 && N == 512) {
        dim3 grid((unsigned)(N / 2 + 1), (unsigned)B);   // 257 x 16 = 4112 blocks
        wbe_fast8<<<grid, TPB>>>(spatial, emb, token, (float*)d_out, N, SP1);
    } else {
        dim3 grid((P + G_ROWS - 1) / G_ROWS, (unsigned)(B * H));
        wbe_generic<<<grid, G_TPB>>>(spatial, emb, token, (float*)d_out, N, H, SP1);
    }
}